// round 3
// baseline (speedup 1.0000x reference)
#include <cuda_runtime.h>
#include <math.h>

// Deterministic two-stage reduction for:
//   l = birth - death (nonfinite -> 0), per diagram
//   t1 = sum l1^2 ; t2 = sum l2^2
//   S0 = sum l0^2 ; M = max l0
//   t01 = 1 - M^2 ; t0 = S0 - M^2 ; loss = t01 + t0 + t1 + t2
// (sum of sortl0[1:]^2 == total sum-of-squares minus one instance of the max.)
//
// Stage 1: NBLK blocks -> partial (s0, s1, s2, m0) in __device__ scratch.
// Stage 2: one block folds partials, writes the 5 output scalars.
// No atomics, no allocations: graph-capturable and bitwise-deterministic.

#define NBLK 2048
#define NTHR 256
#define NWARP (NTHR / 32)

__device__ double g_s0[NBLK];
__device__ double g_s1[NBLK];
__device__ double g_s2[NBLK];
__device__ float  g_m0[NBLK];

__device__ __forceinline__ float bar_len(float b, float d) {
    float l = b - d;
    return isfinite(l) ? l : 0.0f;
}

__device__ __forceinline__ void acc4(double& s, float& m, bool track_max,
                                     float4 v) {
    float l0 = bar_len(v.x, v.y);
    float l1 = bar_len(v.z, v.w);
    s += (double)l0 * (double)l0 + (double)l1 * (double)l1;
    if (track_max) m = fmaxf(m, fmaxf(l0, l1));
}

// Block-level reduction of (3 doubles + 1 float-max) via warp shuffles.
// Result valid in thread 0 of the block.
__device__ __forceinline__ void block_reduce(double& s0, double& s1, double& s2,
                                             float& m0) {
    #pragma unroll
    for (int off = 16; off > 0; off >>= 1) {
        s0 += __shfl_down_sync(0xffffffffu, s0, off);
        s1 += __shfl_down_sync(0xffffffffu, s1, off);
        s2 += __shfl_down_sync(0xffffffffu, s2, off);
        m0 = fmaxf(m0, __shfl_down_sync(0xffffffffu, m0, off));
    }
    __shared__ double w0[NWARP], w1[NWARP], w2[NWARP];
    __shared__ float  wm[NWARP];
    int lane = threadIdx.x & 31;
    int warp = threadIdx.x >> 5;
    if (lane == 0) { w0[warp] = s0; w1[warp] = s1; w2[warp] = s2; wm[warp] = m0; }
    __syncthreads();
    if (warp == 0) {
        s0 = (lane < NWARP) ? w0[lane] : 0.0;
        s1 = (lane < NWARP) ? w1[lane] : 0.0;
        s2 = (lane < NWARP) ? w2[lane] : 0.0;
        m0 = (lane < NWARP) ? wm[lane] : -INFINITY;
        #pragma unroll
        for (int off = NWARP / 2; off > 0; off >>= 1) {
            s0 += __shfl_down_sync(0xffffffffu, s0, off);
            s1 += __shfl_down_sync(0xffffffffu, s1, off);
            s2 += __shfl_down_sync(0xffffffffu, s2, off);
            m0 = fmaxf(m0, __shfl_down_sync(0xffffffffu, m0, off));
        }
    }
}

__global__ __launch_bounds__(NTHR)
void toploss_partial(const float* __restrict__ p0,
                     const float* __restrict__ p1,
                     const float* __restrict__ p2,
                     int n_elems) {
    const float4* d0 = (const float4*)p0;
    const float4* d1 = (const float4*)p1;
    const float4* d2 = (const float4*)p2;
    int n4 = n_elems >> 2;          // float4 chunks (2 bars each)

    double s0 = 0.0, s1 = 0.0, s2 = 0.0;
    float  m0 = -INFINITY;

    int tid    = blockIdx.x * blockDim.x + threadIdx.x;
    int stride = gridDim.x * blockDim.x;

    // Main loop, 2x unrolled: 6 independent LDG.128 issued up front per
    // iteration (MLP_p1 = 6) before the FMA chains consume them.
    int i = tid;
    for (; i + stride < n4; i += 2 * stride) {
        float4 a0 = d0[i];
        float4 b0 = d1[i];
        float4 c0 = d2[i];
        float4 a1 = d0[i + stride];
        float4 b1 = d1[i + stride];
        float4 c1 = d2[i + stride];

        acc4(s0, m0, true,  a0);
        acc4(s1, m0, false, b0);
        acc4(s2, m0, false, c0);
        acc4(s0, m0, true,  a1);
        acc4(s1, m0, false, b1);
        acc4(s2, m0, false, c1);
    }
    if (i < n4) {
        acc4(s0, m0, true,  d0[i]);
        acc4(s1, m0, false, d1[i]);
        acc4(s2, m0, false, d2[i]);
    }

    // Tail: leftover pairs if n_elems not divisible by 4 (defensive).
    int tail_start = n4 << 2;
    if (blockIdx.x == 0 && threadIdx.x == 0) {
        for (int j = tail_start; j + 1 < n_elems; j += 2) {
            float l0 = bar_len(p0[j], p0[j + 1]);
            s0 += (double)l0 * (double)l0;
            m0 = fmaxf(m0, l0);
            float l1 = bar_len(p1[j], p1[j + 1]);
            s1 += (double)l1 * (double)l1;
            float l2 = bar_len(p2[j], p2[j + 1]);
            s2 += (double)l2 * (double)l2;
        }
    }

    block_reduce(s0, s1, s2, m0);
    if (threadIdx.x == 0) {
        g_s0[blockIdx.x] = s0;
        g_s1[blockIdx.x] = s1;
        g_s2[blockIdx.x] = s2;
        g_m0[blockIdx.x] = m0;
    }
}

__global__ __launch_bounds__(NTHR)
void toploss_final(float* __restrict__ out) {
    double s0 = 0.0, s1 = 0.0, s2 = 0.0;
    float  m0 = -INFINITY;

    for (int i = threadIdx.x; i < NBLK; i += NTHR) {
        s0 += g_s0[i];
        s1 += g_s1[i];
        s2 += g_s2[i];
        m0 = fmaxf(m0, g_m0[i]);
    }

    block_reduce(s0, s1, s2, m0);

    if (threadIdx.x == 0) {
        double tops = (double)m0 * (double)m0;
        float t01  = (float)(1.0 - tops);   // sum(1 - top1^2) over one element
        float t0   = (float)(s0 - tops);    // sum l0^2 minus the single max^2
        float t1   = (float)s1;
        float t2   = (float)s2;
        float loss = t01 + t0 + t1 + t2;
        out[0] = loss;
        out[1] = t01;
        out[2] = t0;
        out[3] = t1;
        out[4] = t2;
    }
}

extern "C" void kernel_launch(void* const* d_in, const int* in_sizes, int n_in,
                              void* d_out, int out_size) {
    const float* p0 = (const float*)d_in[0];
    const float* p1 = (const float*)d_in[1];
    const float* p2 = (const float*)d_in[2];
    float* out = (float*)d_out;

    int n_elems = in_sizes[0];   // 8Mi bars * 2 floats = 16,777,216

    toploss_partial<<<NBLK, NTHR>>>(p0, p1, p2, n_elems);
    toploss_final<<<1, NTHR>>>(out);
}